// round 6
// baseline (speedup 1.0000x reference)
#include <cuda_runtime.h>
#include <cuda_bf16.h>
#include <cstdint>

// Problem constants (fixed-shape problem)
#define HIDDEN   128
#define N_NODES  1000000
#define N_GRAPHS 4096

#define ROWS_PER_WARP 64
#define N_WARPSPANS   (N_NODES / ROWS_PER_WARP)   // 15625
#define POOL_THREADS  256
#define POOL_BLOCKS   ((N_WARPSPANS + (POOL_THREADS/32) - 1) / (POOL_THREADS/32))

// Scratch (no cudaMalloc allowed)
__device__ float    g_sums[N_GRAPHS * HIDDEN];
__device__ unsigned g_maxs[N_GRAPHS * HIDDEN];
__device__ int      g_counts[N_GRAPHS];
__device__ int      g_is64;
__device__ float    g_hpart[3 * N_GRAPHS * HIDDEN];   // split-K partials (6.3MB)

// ---- ordered-uint float encoding ----
__device__ __forceinline__ unsigned ordf(float f) {
    unsigned u = __float_as_uint(f);
    return (u & 0x80000000u) ? ~u : (u | 0x80000000u);
}
__device__ __forceinline__ float unordf(unsigned u) {
    return __uint_as_float((u & 0x80000000u) ? (u ^ 0x80000000u) : ~u);
}
#define ORD_NEG_INF 0x007FFFFFu

// ------------------------------------------------------------------
// Kernel 0: init scratch (vectorized) + dtype detect
// ------------------------------------------------------------------
__global__ void init_kernel(const int2* __restrict__ b2) {
    int i = blockIdx.x * blockDim.x + threadIdx.x;     // 0..131071
    ((float4*)g_sums)[i] = make_float4(0.f, 0.f, 0.f, 0.f);
    ((uint4*)g_maxs)[i]  = make_uint4(ORD_NEG_INF, ORD_NEG_INF, ORD_NEG_INF, ORD_NEG_INF);
    if (i < N_GRAPHS) g_counts[i] = 0;
    if (i == 0) {
        int nonzero_hi = 0;
        #pragma unroll
        for (int k = 1; k <= 8; k++) {
            nonzero_hi |= b2[N_NODES / 2 - k].y;
            nonzero_hi |= b2[N_NODES / 4 + k].y;
        }
        g_is64 = (nonzero_hi == 0) ? 1 : 0;
    }
}

// ------------------------------------------------------------------
// Kernel 1: pooling (at HBM roofline — unchanged)
// ------------------------------------------------------------------
__device__ __forceinline__ void flush_seg(int g, float4 a, float4 m, int n, int lane) {
    if ((unsigned)g >= N_GRAPHS) return;
    float*    sp = &g_sums[g * HIDDEN + 4 * lane];
    unsigned* mp = &g_maxs[g * HIDDEN + 4 * lane];
    atomicAdd(sp + 0, a.x);
    atomicAdd(sp + 1, a.y);
    atomicAdd(sp + 2, a.z);
    atomicAdd(sp + 3, a.w);
    atomicMax(mp + 0, ordf(m.x));
    atomicMax(mp + 1, ordf(m.y));
    atomicMax(mp + 2, ordf(m.z));
    atomicMax(mp + 3, ordf(m.w));
    if (lane == 0) atomicAdd(&g_counts[g], n);
}

template <typename IT>
__device__ __forceinline__ void pool_span(const float4* __restrict__ x4,
                                          const IT* __restrict__ batch,
                                          int row0, int lane) {
    const float NEG_INF = -__int_as_float(0x7F800000);
    float4 acc = make_float4(0.f, 0.f, 0.f, 0.f);
    float4 mx  = make_float4(NEG_INF, NEG_INF, NEG_INF, NEG_INF);
    int cur = -1, seglen = 0;

    for (int mb = 0; mb < ROWS_PER_WARP / 8; mb++) {
        int base = row0 + mb * 8;
        int    bb[8];
        float4 vv[8];
        #pragma unroll
        for (int i = 0; i < 8; i++) {
            bb[i] = (int)batch[base + i];
            vv[i] = __ldcs(&x4[(size_t)(base + i) * (HIDDEN / 4) + lane]);
        }
        #pragma unroll
        for (int i = 0; i < 8; i++) {
            int g = bb[i];
            if (g != cur) {
                if (cur >= 0) flush_seg(cur, acc, mx, seglen, lane);
                cur = g;
                acc = make_float4(0.f, 0.f, 0.f, 0.f);
                mx  = make_float4(NEG_INF, NEG_INF, NEG_INF, NEG_INF);
                seglen = 0;
            }
            acc.x += vv[i].x; acc.y += vv[i].y; acc.z += vv[i].z; acc.w += vv[i].w;
            mx.x = fmaxf(mx.x, vv[i].x); mx.y = fmaxf(mx.y, vv[i].y);
            mx.z = fmaxf(mx.z, vv[i].z); mx.w = fmaxf(mx.w, vv[i].w);
            seglen++;
        }
    }
    flush_seg(cur, acc, mx, seglen, lane);
}

__global__ __launch_bounds__(POOL_THREADS)
void pool_kernel(const float4* __restrict__ x4, const void* __restrict__ batch) {
    int wg   = (blockIdx.x * blockDim.x + threadIdx.x) >> 5;
    int lane = threadIdx.x & 31;
    if (wg >= N_WARPSPANS) return;
    int row0 = wg * ROWS_PER_WARP;

    if (g_is64) pool_span<long long>(x4, (const long long*)batch, row0, lane);
    else        pool_span<int>(x4, (const int*)batch, row0, lane);
}

// ------------------------------------------------------------------
// Kernel 2: split-K GEMM stage 1, K-tile = one section (128 rows).
// Grid = 3 sections x 128 graph-groups = 384 blocks x 128 threads.
// Warp owns 8 graphs; lane owns 4 output cols.
// W-LDS total: 1536 warps x 64KB = 98MB (4x less than before).
// ------------------------------------------------------------------
#define S1_GPW 8
#define S1_GPB 32
#define S1_KT  128

__device__ __forceinline__ void ffma2(unsigned long long& acc,
                                      unsigned long long w2,
                                      unsigned long long p2) {
    asm("fma.rn.f32x2 %0, %1, %2, %0;" : "+l"(acc) : "l"(w2), "l"(p2));
}
__device__ __forceinline__ unsigned long long pack2(float p) {
    unsigned long long r;
    asm("mov.b64 %0, {%1, %1};" : "=l"(r) : "r"(__float_as_uint(p)));
    return r;
}

__global__ __launch_bounds__(128)
void gemm_stage1(const float* __restrict__ W) {
    __shared__ float Ws[S1_KT * HIDDEN];     // 64 KB
    __shared__ float Ps[S1_GPB][S1_KT];      // 16 KB

    int sec  = blockIdx.x >> 7;              // 0=mean 1=max 2=sum
    int grp  = blockIdx.x & 127;
    int g0   = grp * S1_GPB;
    int tid  = threadIdx.x;                  // 128
    int warp = tid >> 5, lane = tid & 31;

    // W section tile: 128 rows x 128 cols = 4096 float4 over 128 threads
    const float4* Wg = (const float4*)(W + sec * S1_KT * HIDDEN);
    #pragma unroll
    for (int i = 0; i < 32; i++) ((float4*)Ws)[tid + i * 128] = Wg[tid + i * 128];

    // build Ps for this warp's 8 graphs (section uniform per block)
    #pragma unroll
    for (int g = 0; g < S1_GPW; g++) {
        int gl  = warp * S1_GPW + g;
        int gg  = g0 + gl;
        int cnt = g_counts[gg];
        float inv = 1.0f / fmaxf((float)cnt, 1.0f);
        #pragma unroll
        for (int h = 0; h < 4; h++) {
            int c = h * 32 + lane;           // 0..127
            float v;
            if (sec == 0)      v = g_sums[gg * HIDDEN + c] * inv;
            else if (sec == 1) v = (cnt > 0) ? unordf(g_maxs[gg * HIDDEN + c]) : 0.f;
            else               v = g_sums[gg * HIDDEN + c];
            Ps[gl][c] = v;
        }
    }
    __syncthreads();

    unsigned long long acc[S1_GPW][2];
    #pragma unroll
    for (int g = 0; g < S1_GPW; g++) { acc[g][0] = 0ull; acc[g][1] = 0ull; }

    int glb = warp * S1_GPW;
    #pragma unroll 2
    for (int k4 = 0; k4 < S1_KT / 4; k4++) {
        float4 pv[S1_GPW];
        #pragma unroll
        for (int g = 0; g < S1_GPW; g++)
            pv[g] = ((const float4*)Ps[glb + g])[k4];          // broadcast LDS.128
        #pragma unroll
        for (int kk = 0; kk < 4; kk++) {
            ulonglong2 w2 = ((const ulonglong2*)(Ws + (k4 * 4 + kk) * HIDDEN))[lane];
            #pragma unroll
            for (int g = 0; g < S1_GPW; g++) {
                float p = (kk == 0) ? pv[g].x : (kk == 1) ? pv[g].y
                        : (kk == 2) ? pv[g].z : pv[g].w;
                unsigned long long p2 = pack2(p);
                ffma2(acc[g][0], w2.x, p2);
                ffma2(acc[g][1], w2.y, p2);
            }
        }
    }

    // write partials: coalesced STG.128, no atomics
    #pragma unroll
    for (int g = 0; g < S1_GPW; g++) {
        int gg = g0 + glb + g;
        float4 o;
        unsigned lo, hi;
        asm("mov.b64 {%0, %1}, %2;" : "=r"(lo), "=r"(hi) : "l"(acc[g][0]));
        o.x = __uint_as_float(lo); o.y = __uint_as_float(hi);
        asm("mov.b64 {%0, %1}, %2;" : "=r"(lo), "=r"(hi) : "l"(acc[g][1]));
        o.z = __uint_as_float(lo); o.w = __uint_as_float(hi);
        ((float4*)g_hpart)[((size_t)sec * N_GRAPHS + gg) * (HIDDEN / 4) + lane] = o;
    }
}

// ------------------------------------------------------------------
// Kernel 3: stage 2 — reduce 3 partials + bias + LayerNorm + GELU.
// ------------------------------------------------------------------
__global__ __launch_bounds__(256)
void gemm_stage2(const float* __restrict__ bias, const float* __restrict__ gamma,
                 const float* __restrict__ beta, float* __restrict__ out) {
    int tid  = threadIdx.x;
    int warp = tid >> 5, lane = tid & 31;
    int g    = blockIdx.x * 8 + warp;

    float4 b4 = ((const float4*)bias)[lane];
    float4 gm = ((const float4*)gamma)[lane];
    float4 bt = ((const float4*)beta)[lane];

    float4 h4 = make_float4(b4.x, b4.y, b4.z, b4.w);
    #pragma unroll
    for (int sec = 0; sec < 3; sec++) {
        float4 p = ((const float4*)g_hpart)[((size_t)sec * N_GRAPHS + g) * (HIDDEN / 4) + lane];
        h4.x += p.x; h4.y += p.y; h4.z += p.z; h4.w += p.w;
    }

    float s = h4.x + h4.y + h4.z + h4.w;
    #pragma unroll
    for (int o = 16; o; o >>= 1) s += __shfl_xor_sync(0xFFFFFFFFu, s, o);
    float mu = s * (1.0f / 128.0f);

    float d0 = h4.x - mu, d1 = h4.y - mu, d2 = h4.z - mu, d3 = h4.w - mu;
    float v = d0*d0 + d1*d1 + d2*d2 + d3*d3;
    #pragma unroll
    for (int o = 16; o; o >>= 1) v += __shfl_xor_sync(0xFFFFFFFFu, v, o);
    float rstd = rsqrtf(v * (1.0f / 128.0f) + 1e-5f);

    float hh[4] = {h4.x, h4.y, h4.z, h4.w};
    float gmv[4] = {gm.x, gm.y, gm.z, gm.w};
    float btv[4] = {bt.x, bt.y, bt.z, bt.w};
    float4 o4;
    float* ov = (float*)&o4;
    #pragma unroll
    for (int k = 0; k < 4; k++) {
        float t = (hh[k] - mu) * rstd * gmv[k] + btv[k];
        ov[k] = 0.5f * t * (1.0f + erff(t * 0.70710678118654752f));
    }
    ((float4*)out)[(size_t)g * (HIDDEN / 4) + lane] = o4;
}

// ------------------------------------------------------------------
extern "C" void kernel_launch(void* const* d_in, const int* in_sizes, int n_in,
                              void* d_out, int out_size) {
    const float* x     = nullptr;
    const void*  batch = nullptr;
    const float* W     = nullptr;
    const float* b     = nullptr;
    const float* gamma = nullptr;
    const float* beta  = nullptr;

    for (int i = 0; i < n_in; i++) {
        int s = in_sizes[i];
        if (s == N_NODES * HIDDEN)         x = (const float*)d_in[i];
        else if (s == N_NODES)             batch = d_in[i];
        else if (s == 3 * HIDDEN * HIDDEN) W = (const float*)d_in[i];
        else if (s == HIDDEN) {
            if (!b) b = (const float*)d_in[i];
            else if (!gamma) gamma = (const float*)d_in[i];
            else if (!beta)  beta = (const float*)d_in[i];
        }
    }

    init_kernel<<<512, 256>>>((const int2*)batch);
    pool_kernel<<<POOL_BLOCKS, POOL_THREADS>>>((const float4*)x, batch);
    gemm_stage1<<<3 * 128, 128>>>(W);
    gemm_stage2<<<N_GRAPHS / 8, 256>>>(b, gamma, beta, (float*)d_out);
}

// round 8
// speedup vs baseline: 1.1166x; 1.1166x over previous
#include <cuda_runtime.h>
#include <cuda_bf16.h>
#include <cstdint>

// Problem constants (fixed-shape problem)
#define HIDDEN   128
#define N_NODES  1000000
#define N_GRAPHS 4096

#define ROWS_PER_WARP 64
#define N_WARPSPANS   (N_NODES / ROWS_PER_WARP)   // 15625
#define POOL_THREADS  256
#define POOL_BLOCKS   ((N_WARPSPANS + (POOL_THREADS/32) - 1) / (POOL_THREADS/32))

// Scratch (no cudaMalloc). Explicitly initialized by init_kernel every call.
__device__ float    g_sums[N_GRAPHS * HIDDEN];
__device__ unsigned g_maxs[N_GRAPHS * HIDDEN];
__device__ int      g_counts[N_GRAPHS];
__device__ float    g_h[N_GRAPHS * HIDDEN];      // GEMM accumulators (REDG)

// ---- ordered-uint float encoding (proven R2-R6 variant) ----
__device__ __forceinline__ unsigned ordf(float f) {
    unsigned u = __float_as_uint(f);
    return (u & 0x80000000u) ? ~u : (u | 0x80000000u);
}
__device__ __forceinline__ float unordf(unsigned u) {
    return __uint_as_float((u & 0x80000000u) ? (u ^ 0x80000000u) : ~u);
}
#define ORD_NEG_INF 0x007FFFFFu

// ------------------------------------------------------------------
// Kernel 0: init all scratch (vectorized). 512 blocks x 256 threads.
// ------------------------------------------------------------------
__global__ void init_kernel() {
    int i = blockIdx.x * blockDim.x + threadIdx.x;     // 0..131071
    ((float4*)g_sums)[i] = make_float4(0.f, 0.f, 0.f, 0.f);
    ((float4*)g_h)[i]    = make_float4(0.f, 0.f, 0.f, 0.f);
    ((uint4*)g_maxs)[i]  = make_uint4(ORD_NEG_INF, ORD_NEG_INF, ORD_NEG_INF, ORD_NEG_INF);
    if (i < N_GRAPHS) g_counts[i] = 0;
}

// ------------------------------------------------------------------
// Kernel 1: pooling (proven; ~88% of HBM roofline). Inline dtype probe.
// ------------------------------------------------------------------
__device__ __forceinline__ void flush_seg(int g, float4 a, float4 m, int n, int lane) {
    if ((unsigned)g >= N_GRAPHS) return;
    float*    sp = &g_sums[g * HIDDEN + 4 * lane];
    unsigned* mp = &g_maxs[g * HIDDEN + 4 * lane];
    atomicAdd(sp + 0, a.x);
    atomicAdd(sp + 1, a.y);
    atomicAdd(sp + 2, a.z);
    atomicAdd(sp + 3, a.w);
    atomicMax(mp + 0, ordf(m.x));
    atomicMax(mp + 1, ordf(m.y));
    atomicMax(mp + 2, ordf(m.z));
    atomicMax(mp + 3, ordf(m.w));
    if (lane == 0) atomicAdd(&g_counts[g], n);
}

template <typename IT>
__device__ __forceinline__ void pool_span(const float4* __restrict__ x4,
                                          const IT* __restrict__ batch,
                                          int row0, int lane) {
    const float NEG_INF = -__int_as_float(0x7F800000);
    float4 acc = make_float4(0.f, 0.f, 0.f, 0.f);
    float4 mx  = make_float4(NEG_INF, NEG_INF, NEG_INF, NEG_INF);
    int cur = -1, seglen = 0;

    for (int mb = 0; mb < ROWS_PER_WARP / 8; mb++) {
        int base = row0 + mb * 8;
        int    bb[8];
        float4 vv[8];
        #pragma unroll
        for (int i = 0; i < 8; i++) {
            bb[i] = (int)batch[base + i];
            vv[i] = __ldcs(&x4[(size_t)(base + i) * (HIDDEN / 4) + lane]);
        }
        #pragma unroll
        for (int i = 0; i < 8; i++) {
            int g = bb[i];
            if (g != cur) {
                if (cur >= 0) flush_seg(cur, acc, mx, seglen, lane);
                cur = g;
                acc = make_float4(0.f, 0.f, 0.f, 0.f);
                mx  = make_float4(NEG_INF, NEG_INF, NEG_INF, NEG_INF);
                seglen = 0;
            }
            acc.x += vv[i].x; acc.y += vv[i].y; acc.z += vv[i].z; acc.w += vv[i].w;
            mx.x = fmaxf(mx.x, vv[i].x); mx.y = fmaxf(mx.y, vv[i].y);
            mx.z = fmaxf(mx.z, vv[i].z); mx.w = fmaxf(mx.w, vv[i].w);
            seglen++;
        }
    }
    flush_seg(cur, acc, mx, seglen, lane);
}

__global__ __launch_bounds__(POOL_THREADS)
void pool_kernel(const float4* __restrict__ x4, const void* __restrict__ batch) {
    int wg   = (blockIdx.x * blockDim.x + threadIdx.x) >> 5;
    int lane = threadIdx.x & 31;
    if (wg >= N_WARPSPANS) return;
    int row0 = wg * ROWS_PER_WARP;

    // inline dtype probe: sorted ids < 4096 => int64 high words all zero
    const int2* b2 = (const int2*)batch;
    int nz = 0;
    #pragma unroll
    for (int k = 1; k <= 8; k++) {
        nz |= b2[N_NODES / 2 - k].y;
        nz |= b2[N_NODES / 4 + k].y;
    }
    if (nz == 0) pool_span<long long>(x4, (const long long*)batch, row0, lane);
    else         pool_span<int>(x4, (const int*)batch, row0, lane);
}

// ------------------------------------------------------------------
// Kernel 2: split-K GEMM, occupancy-maximized.
// Grid = 12 k-tiles(32 rows) x 256 graph-groups(16) = 3072 blocks x 128thr.
// Warp owns 4 graphs; lane owns 4 output cols. Partials REDG into g_h.
// 18KB smem + <=64 regs -> ~8-9 blocks/SM (~32-36 warps/SM).
// ------------------------------------------------------------------
#define S1_KT   32
#define S1_GPB  16
#define S1_GPW  4
#define N_KT    12

__device__ __forceinline__ void ffma2(unsigned long long& acc,
                                      unsigned long long w2,
                                      unsigned long long p2) {
    asm("fma.rn.f32x2 %0, %1, %2, %0;" : "+l"(acc) : "l"(w2), "l"(p2));
}
__device__ __forceinline__ unsigned long long pack2(float p) {
    unsigned long long r;
    asm("mov.b64 %0, {%1, %1};" : "=l"(r) : "r"(__float_as_uint(p)));
    return r;
}

__global__ __launch_bounds__(128, 8)
void gemm_stage1(const float* __restrict__ W) {
    __shared__ float Ws[S1_KT * HIDDEN];      // 16 KB
    __shared__ float Ps[S1_GPB][S1_KT];       // 2 KB

    int kt   = blockIdx.x / 256;               // 0..11
    int grp  = blockIdx.x % 256;               // 0..255
    int g0   = grp * S1_GPB;
    int tid  = threadIdx.x;                    // 128
    int warp = tid >> 5, lane = tid & 31;
    int glb  = warp * S1_GPW;

    // W tile: 32 rows x 128 cols = 1024 float4 over 128 threads
    const float4* Wg = (const float4*)(W + kt * S1_KT * HIDDEN);
    #pragma unroll
    for (int i = 0; i < 8; i++) ((float4*)Ws)[tid + i * 128] = Wg[tid + i * 128];

    // Ps: warp's 4 graphs x 32 pooled values. tiles 0-3 mean, 4-7 max, 8-11 sum
    int sec = kt >> 2;
    int lc  = (kt & 3) * 32 + lane;            // col within section, 0..127
    #pragma unroll
    for (int g = 0; g < S1_GPW; g++) {
        int gg  = g0 + glb + g;
        int cnt = g_counts[gg];
        float v;
        if (sec == 0)      v = g_sums[gg * HIDDEN + lc] * (1.0f / fmaxf((float)cnt, 1.0f));
        else if (sec == 1) v = (cnt > 0) ? unordf(g_maxs[gg * HIDDEN + lc]) : 0.f;
        else               v = g_sums[gg * HIDDEN + lc];
        Ps[glb + g][lane] = v;
    }
    __syncthreads();

    unsigned long long acc[S1_GPW][2];
    #pragma unroll
    for (int g = 0; g < S1_GPW; g++) { acc[g][0] = 0ull; acc[g][1] = 0ull; }

    #pragma unroll
    for (int k4 = 0; k4 < S1_KT / 4; k4++) {
        float4 pv[S1_GPW];
        #pragma unroll
        for (int g = 0; g < S1_GPW; g++)
            pv[g] = ((const float4*)Ps[glb + g])[k4];           // broadcast LDS.128
        #pragma unroll
        for (int kk = 0; kk < 4; kk++) {
            ulonglong2 w2 = ((const ulonglong2*)(Ws + (k4 * 4 + kk) * HIDDEN))[lane];
            #pragma unroll
            for (int g = 0; g < S1_GPW; g++) {
                float p = (kk == 0) ? pv[g].x : (kk == 1) ? pv[g].y
                        : (kk == 2) ? pv[g].z : pv[g].w;
                unsigned long long p2 = pack2(p);
                ffma2(acc[g][0], w2.x, p2);
                ffma2(acc[g][1], w2.y, p2);
            }
        }
    }

    // REDG partial accumulation into zero-initialized g_h
    #pragma unroll
    for (int g = 0; g < S1_GPW; g++) {
        int gg = g0 + glb + g;
        float* hp = &g_h[gg * HIDDEN + 4 * lane];
        unsigned lo, hi;
        asm("mov.b64 {%0, %1}, %2;" : "=r"(lo), "=r"(hi) : "l"(acc[g][0]));
        atomicAdd(hp + 0, __uint_as_float(lo));
        atomicAdd(hp + 1, __uint_as_float(hi));
        asm("mov.b64 {%0, %1}, %2;" : "=r"(lo), "=r"(hi) : "l"(acc[g][1]));
        atomicAdd(hp + 2, __uint_as_float(lo));
        atomicAdd(hp + 3, __uint_as_float(hi));
    }
}

// ------------------------------------------------------------------
// Kernel 3: finisher — bias + LayerNorm + exact GELU.
// 512 blocks x 256 threads; warp = 1 graph; lane = 4 cols.
// ------------------------------------------------------------------
__global__ __launch_bounds__(256)
void finish_kernel(const float* __restrict__ bias, const float* __restrict__ gamma,
                   const float* __restrict__ beta, float* __restrict__ out) {
    int tid  = threadIdx.x;
    int warp = tid >> 5, lane = tid & 31;
    int g    = blockIdx.x * 8 + warp;

    float4 b4 = ((const float4*)bias)[lane];
    float4 gm = ((const float4*)gamma)[lane];
    float4 bt = ((const float4*)beta)[lane];

    float4 p = ((const float4*)g_h)[(size_t)g * (HIDDEN / 4) + lane];
    float h[4];
    h[0] = p.x + b4.x; h[1] = p.y + b4.y; h[2] = p.z + b4.z; h[3] = p.w + b4.w;

    float s = h[0] + h[1] + h[2] + h[3];
    #pragma unroll
    for (int o = 16; o; o >>= 1) s += __shfl_xor_sync(0xFFFFFFFFu, s, o);
    float mu = s * (1.0f / 128.0f);

    float d0 = h[0]-mu, d1 = h[1]-mu, d2 = h[2]-mu, d3 = h[3]-mu;
    float v = d0*d0 + d1*d1 + d2*d2 + d3*d3;
    #pragma unroll
    for (int o = 16; o; o >>= 1) v += __shfl_xor_sync(0xFFFFFFFFu, v, o);
    float rstd = rsqrtf(v * (1.0f / 128.0f) + 1e-5f);

    float gmv[4] = {gm.x, gm.y, gm.z, gm.w};
    float btv[4] = {bt.x, bt.y, bt.z, bt.w};
    float4 o4;
    float* ov = (float*)&o4;
    #pragma unroll
    for (int k = 0; k < 4; k++) {
        float t = (h[k] - mu) * rstd * gmv[k] + btv[k];
        ov[k] = 0.5f * t * (1.0f + erff(t * 0.70710678118654752f));
    }
    ((float4*)out)[(size_t)g * (HIDDEN / 4) + lane] = o4;
}

// ------------------------------------------------------------------
extern "C" void kernel_launch(void* const* d_in, const int* in_sizes, int n_in,
                              void* d_out, int out_size) {
    const float* x     = nullptr;
    const void*  batch = nullptr;
    const float* W     = nullptr;
    const float* b     = nullptr;
    const float* gamma = nullptr;
    const float* beta  = nullptr;

    for (int i = 0; i < n_in; i++) {
        int s = in_sizes[i];
        if (s == N_NODES * HIDDEN)         x = (const float*)d_in[i];
        else if (s == N_NODES)             batch = d_in[i];
        else if (s == 3 * HIDDEN * HIDDEN) W = (const float*)d_in[i];
        else if (s == HIDDEN) {
            if (!b) b = (const float*)d_in[i];
            else if (!gamma) gamma = (const float*)d_in[i];
            else if (!beta)  beta = (const float*)d_in[i];
        }
    }

    init_kernel<<<512, 256>>>();
    pool_kernel<<<POOL_BLOCKS, POOL_THREADS>>>((const float4*)x, batch);
    gemm_stage1<<<N_KT * 256, 128>>>(W);
    finish_kernel<<<N_GRAPHS / 8, 256>>>(b, gamma, beta, (float*)d_out);
}